// round 7
// baseline (speedup 1.0000x reference)
#include <cuda_runtime.h>
#include <math.h>

#define G    512
#define NPG  90
#define NTOT (G*NPG)      // 46080
#define FIN  90
#define HC   64
#define KP   70
#define POOLW (KP*HC)     // 4480
#define APAD 92           // padded A row (float4-able)

// ---------------- scratch (device globals; referenced ONLY in device code) --
__device__ float g_A[G*NPG*NPG];     // RAW edge counts (row = dst), 16.6MB
__device__ float g_PQ[NTOT*128];     // [x@W1l | x@W1r]
__device__ float g_H1[NTOT*HC];      // conv1 output (x_train)
__device__ float g_RW[NTOT*128];     // [relu(h1)@W2l | relu(h1)@W2r]
__device__ float g_H2[NTOT*HC];      // conv2 output
__device__ float g_pool[G*POOLW];    // sort-pooled features
__device__ int   g_mode;             // 1 = edge data is int64 (odd words zero)

// ---------------- edge dtype detection (one warp, ballot) -------------------
__global__ void detect_kernel(const int* __restrict__ ei) {
    int lane = threadIdx.x;
    int nz = 0;
    for (int i = lane; i < 512; i += 32) nz |= ei[2*i + 1];
    unsigned any = __ballot_sync(0xffffffffu, nz != 0);
    if (lane == 0) g_mode = (any == 0);
}

// ---------------- adjacency build ------------------------------------------
__global__ void zeroA_kernel() {
    int n = G*NPG*NPG/4;
    float4* p = (float4*)g_A;
    float4 z = make_float4(0.f, 0.f, 0.f, 0.f);
    for (int i = blockIdx.x*blockDim.x + threadIdx.x; i < n; i += gridDim.x*blockDim.x)
        p[i] = z;
}

__global__ void edge_kernel(const int* __restrict__ ei, int E) {
    int e = blockIdx.x*blockDim.x + threadIdx.x;
    if (e >= E) return;
    int s, d;
    if (g_mode) { s = ei[2*e]; d = ei[2*(E + e)]; }   // int64 storage
    else        { s = ei[e];   d = ei[E + e];      }  // int32 storage
    if ((unsigned)s >= NTOT || (unsigned)d >= NTOT) return;
    int g  = d / NPG;
    int sl = s - g*NPG;
    int dl = d - g*NPG;
    if ((unsigned)sl >= NPG) return;
    atomicAdd(&g_A[(size_t)(g*NPG + dl)*NPG + sl], 1.0f);
}

// ---------------- node GEMM: X[N,KD] @ [Wl|Wr] -> sel{g_PQ,g_RW}[N,128] -----
// INSEL: 0 = external pointer X (conv1), 1 = internal g_H1 (conv2)
template<int KD, bool RELU, int INSEL, int OUTSEL>
__global__ __launch_bounds__(256) void gemm_node(const float* __restrict__ Xext,
                                                 const float* __restrict__ Wl,
                                                 const float* __restrict__ Wr) {
    __shared__ float ws[32*128];
    __shared__ float xs[32*KD];
    const float* X = INSEL ? (const float*)g_H1 : Xext;
    float* out = OUTSEL ? g_RW : g_PQ;
    int t = threadIdx.x;
    int r0blk = blockIdx.x * 32;

    for (int idx = t; idx < 32*KD; idx += 256) {
        int r = idx / KD, k = idx - r*KD;
        float v = X[(size_t)(r0blk + r)*KD + k];
        if (RELU) v = fmaxf(v, 0.f);
        xs[idx] = v;
    }

    int tx = t & 31, ty = t >> 5;
    int c0 = tx*4, r0 = ty*4;
    float acc[4][4];
    #pragma unroll
    for (int i = 0; i < 4; i++)
        #pragma unroll
        for (int j = 0; j < 4; j++) acc[i][j] = 0.f;

    for (int kt = 0; kt < KD; kt += 32) {
        int kc = (KD - kt < 32) ? (KD - kt) : 32;
        __syncthreads();                       // also covers xs on first pass
        for (int idx = t; idx < kc*128; idx += 256) {
            int k = idx >> 7, c = idx & 127;
            ws[idx] = (c < 64) ? Wl[(kt + k)*64 + c] : Wr[(kt + k)*64 + (c - 64)];
        }
        __syncthreads();
        for (int k = 0; k < kc; k++) {
            float4 b = *(const float4*)&ws[k*128 + c0];
            float a0 = xs[(r0+0)*KD + kt + k];
            float a1 = xs[(r0+1)*KD + kt + k];
            float a2 = xs[(r0+2)*KD + kt + k];
            float a3 = xs[(r0+3)*KD + kt + k];
            acc[0][0]+=a0*b.x; acc[0][1]+=a0*b.y; acc[0][2]+=a0*b.z; acc[0][3]+=a0*b.w;
            acc[1][0]+=a1*b.x; acc[1][1]+=a1*b.y; acc[1][2]+=a1*b.z; acc[1][3]+=a1*b.w;
            acc[2][0]+=a2*b.x; acc[2][1]+=a2*b.y; acc[2][2]+=a2*b.z; acc[2][3]+=a2*b.w;
            acc[3][0]+=a3*b.x; acc[3][1]+=a3*b.y; acc[3][2]+=a3*b.z; acc[3][3]+=a3*b.w;
        }
    }
    #pragma unroll
    for (int i = 0; i < 4; i++) {
        float4 v = make_float4(acc[i][0], acc[i][1], acc[i][2], acc[i][3]);
        *(float4*)&out[(size_t)(r0blk + r0 + i)*128 + c0] = v;
    }
}

// ---------------- per-graph aggregation: out = mean + skip + bias -----------
// Raw counts in g_A; row sums + inverse computed in-block (no norm pass).
// A rows padded to 92 floats in smem -> float4 inner loop over j.
// INSEL: 0=g_PQ 1=g_RW ; OUTSEL: 0=g_H1 1=g_H2 ; optional extra dst (x_train)
template<int INSEL, int OUTSEL>
__global__ __launch_bounds__(256) void aggr_kernel(const float* __restrict__ bias,
                                                   float* __restrict__ extra) {
    __shared__ float As[NPG*APAD];   // 33120B
    __shared__ float inv[NPG];
    const float* PQ = INSEL ? g_RW : g_PQ;
    float* out = OUTSEL ? g_H2 : g_H1;
    int g = blockIdx.x;
    int t = threadIdx.x;

    for (int idx = t; idx < NPG*NPG; idx += 256) {
        int row = idx / NPG, col = idx - row*NPG;
        As[row*APAD + col] = g_A[(size_t)g*NPG*NPG + idx];
    }
    // zero pad columns 90,91 so float4 tail group is harmless if touched
    if (t < NPG*2) {
        int row = t >> 1, col = NPG + (t & 1);
        As[row*APAD + col] = 0.f;
    }
    __syncthreads();

    // per-row sums -> inv (8 warps sweep 90 rows)
    {
        int wid = t >> 5, lane = t & 31;
        for (int row = wid; row < NPG; row += 8) {
            float s = 0.f;
            for (int j = lane; j < NPG; j += 32) s += As[row*APAD + j];
            #pragma unroll
            for (int o = 16; o; o >>= 1) s += __shfl_xor_sync(0xffffffffu, s, o);
            if (lane == 0) inv[row] = 1.0f / fmaxf(s, 1.0f);
        }
    }
    __syncthreads();

    int c = t & 63, rg = t >> 6;      // 4 row-groups: rows rg, rg+4, ...
    float acc[23];
    #pragma unroll
    for (int i = 0; i < 23; i++) acc[i] = 0.f;

    const float* Pg = PQ + (size_t)g*NPG*128;

    // main: j in steps of 4 (22 groups cover j=0..87)
    for (int j = 0; j < 88; j += 4) {
        float w0 = __ldg(&Pg[(j+0)*128 + c]);
        float w1 = __ldg(&Pg[(j+1)*128 + c]);
        float w2 = __ldg(&Pg[(j+2)*128 + c]);
        float w3 = __ldg(&Pg[(j+3)*128 + c]);
        #pragma unroll
        for (int i = 0; i < 23; i++) {
            int row = rg + 4*i;
            if (row < NPG) {
                float4 a = *(const float4*)&As[row*APAD + j];
                acc[i] += a.x*w0 + a.y*w1 + a.z*w2 + a.w*w3;
            }
        }
    }
    // tail j = 88, 89
    {
        float w0 = __ldg(&Pg[88*128 + c]);
        float w1 = __ldg(&Pg[89*128 + c]);
        #pragma unroll
        for (int i = 0; i < 23; i++) {
            int row = rg + 4*i;
            if (row < NPG)
                acc[i] += As[row*APAD + 88]*w0 + As[row*APAD + 89]*w1;
        }
    }

    float bc = bias[c];
    #pragma unroll
    for (int i = 0; i < 23; i++) {
        int row = rg + 4*i;
        if (row < NPG) {
            int n = g*NPG + row;
            float v = acc[i]*inv[row] + Pg[row*128 + 64 + c] + bc;
            out[(size_t)n*HC + c] = v;
            if (extra) extra[(size_t)n*HC + c] = v;
        }
    }
}

// ---------------- sort-pool: top-70 by channel 63, stable desc --------------
__global__ void sortpool_kernel() {
    __shared__ float key[NPG];
    __shared__ int   slot[KP];
    int g = blockIdx.x, t = threadIdx.x;
    if (t < NPG) key[t] = g_H2[(size_t)(g*NPG + t)*HC + 63];
    __syncthreads();
    if (t < NPG) {
        float v = key[t];
        int rank = 0;
        for (int j = 0; j < NPG; j++) {
            float u = key[j];
            rank += (u > v) || (u == v && j < t);
        }
        if (rank < KP) slot[rank] = t;
    }
    __syncthreads();
    for (int idx = t; idx < POOLW; idx += 128) {
        int r = idx >> 6, c = idx & 63;
        g_pool[(size_t)g*POOLW + idx] = g_H2[(size_t)(g*NPG + slot[r])*HC + c];
    }
}

// ---------------- final: pool @ Wl1 + bl1, @ Wl2 + bl2, sigmoid -------------
__global__ __launch_bounds__(256) void final_kernel(const float* __restrict__ Wl1,
                                                    const float* __restrict__ bl1,
                                                    const float* __restrict__ Wl2,
                                                    const float* __restrict__ bl2,
                                                    float* __restrict__ outG) {
    __shared__ float ws[64*64];
    __shared__ float ps[8*64];
    __shared__ float pbuf[8*64];
    int t = threadIdx.x;
    int g0 = blockIdx.x * 8;
    int c = t & 63, gi = t >> 6;       // gi in 0..3, handles graphs gi and gi+4
    float acc0 = 0.f, acc1 = 0.f;

    for (int chunk = 0; chunk < POOLW/64; chunk++) {
        int m0 = chunk*64;
        __syncthreads();
        for (int idx = t; idx < 64*64; idx += 256)
            ws[idx] = Wl1[(size_t)(m0 + (idx >> 6))*64 + (idx & 63)];
        for (int idx = t; idx < 8*64; idx += 256) {
            int gg = idx >> 6, mm = idx & 63;
            ps[idx] = g_pool[(size_t)(g0 + gg)*POOLW + m0 + mm];
        }
        __syncthreads();
        #pragma unroll
        for (int kk = 0; kk < 64; kk++) {
            float w = ws[kk*64 + c];
            acc0 += ps[gi*64 + kk] * w;
            acc1 += ps[(gi+4)*64 + kk] * w;
        }
    }
    __syncthreads();
    pbuf[gi*64 + c]     = acc0 + bl1[c];
    pbuf[(gi+4)*64 + c] = acc1 + bl1[c];
    __syncthreads();
    int w = t >> 5, lane = t & 31;     // 8 warps -> 8 graphs
    float v = pbuf[w*64 + lane]*Wl2[lane] + pbuf[w*64 + lane + 32]*Wl2[lane + 32];
    #pragma unroll
    for (int o = 16; o; o >>= 1) v += __shfl_xor_sync(0xffffffffu, v, o);
    if (lane == 0) outG[g0 + w] = 1.f / (1.f + expf(-(v + bl2[0])));
}

// ---------------------------------------------------------------------------
// kernel_launch: identify inputs by SIZE SIGNATURE (robust to metadata order),
// then kernel launches only. NO device-symbol addresses cross host/device.
extern "C" void kernel_launch(void* const* d_in, const int* in_sizes, int n_in,
                              void* d_out, int out_size) {
    const float *x = 0, *W1l = 0, *W1r = 0, *W2l = 0, *W2r = 0;
    const float *Wl1 = 0, *bl2 = 0;
    const int   *ei = 0;
    int i5760 = 0, i4096 = 0;
    int idx64[8]; int n64 = 0;

    for (int i = 0; i < n_in; i++) {
        int sz = in_sizes[i];
        const float* p = (const float*)d_in[i];
        switch (sz) {
            case 4147200: x   = p; break;                       // [46080,90]
            case 1843200: ei  = (const int*)d_in[i]; break;     // [2,921600]
            case  286720: Wl1 = p; break;                       // [4480,64]
            case    5760: if (i5760++ == 0) W1l = p; else W1r = p; break;
            case    4096: if (i4096++ == 0) W2l = p; else W2r = p; break;
            case      64: if (n64 < 8) idx64[n64++] = i; break; // b1,b2,bl1,Wl2
            case       1: bl2 = p; break;
            default: break;                                     // batch unused
        }
    }
    const float *b1, *b2, *bl1, *Wl2;
    if (n_in > 0 && in_sizes[0] == 5760) {          // alphabetical (W* first)
        Wl2 = (const float*)d_in[idx64[0]];
        b1  = (const float*)d_in[idx64[1]];
        b2  = (const float*)d_in[idx64[2]];
        bl1 = (const float*)d_in[idx64[3]];
    } else {                                        // dict / signature order
        b1  = (const float*)d_in[idx64[0]];
        b2  = (const float*)d_in[idx64[1]];
        bl1 = (const float*)d_in[idx64[2]];
        Wl2 = (const float*)d_in[idx64[3]];
    }

    float* outG = (float*)d_out;            // [512] sigmoid outputs
    float* xtp  = (out_size >= G + NTOT*HC) ? (float*)d_out + G : (float*)0;
    int E = 1843200 / 2;

    // 1. adjacency: detect dtype, zero, count (raw counts; no norm pass)
    detect_kernel<<<1, 32>>>(ei);
    zeroA_kernel<<<2048, 512>>>();
    edge_kernel<<<(E + 255)/256, 256>>>(ei, E);

    // 2. conv1: projections -> g_PQ; aggregation -> g_H1 (+ d_out tail)
    gemm_node<90, false, 0, 0><<<NTOT/32, 256>>>(x, W1l, W1r);
    aggr_kernel<0, 0><<<G, 256>>>(b1, xtp);

    // 3. conv2: input g_H1 selected inside kernel (relu on load) -> g_RW
    gemm_node<64, true, 1, 1><<<NTOT/32, 256>>>((const float*)0, W2l, W2r);
    aggr_kernel<1, 1><<<G, 256>>>(b2, (float*)0);

    // 4. sort-pool + MLP head
    sortpool_kernel<<<G, 128>>>();
    final_kernel<<<G/8, 256>>>(Wl1, bl1, Wl2, bl2, outG);
}

// round 8
// speedup vs baseline: 1.3401x; 1.3401x over previous
#include <cuda_runtime.h>
#include <math.h>
#include <stdint.h>

#define G    512
#define NPG  90
#define NTOT (G*NPG)      // 46080
#define FIN  90
#define HC   64
#define KP   70
#define POOLW (KP*HC)     // 4480
#define APAD 92           // padded A row (float4-able)

// ---------------- scratch (device globals; referenced ONLY in device code) --
__device__ float g_A[G*NPG*NPG];     // RAW edge counts (row = dst), 16.6MB
__device__ float g_PQ[NTOT*128];     // [x@W1l | x@W1r]
__device__ float g_H1[NTOT*HC];      // conv1 output (x_train)
__device__ float g_RW[NTOT*128];     // [relu(h1)@W2l | relu(h1)@W2r]
__device__ float g_pool[G*POOLW];    // sort-pooled features
__device__ int   g_mode;             // 1 = edge data is int64 (odd words zero)

// ---------------- tf32 helpers ----------------------------------------------
__device__ __forceinline__ uint32_t f2tf32(float x) {
    uint32_t r;
    asm("cvt.rna.tf32.f32 %0, %1;" : "=r"(r) : "f"(x));
    return r;
}
__device__ __forceinline__ void split_tf32(float x, uint32_t& hi, uint32_t& lo) {
    hi = f2tf32(x);
    lo = f2tf32(x - __uint_as_float(hi));
}
__device__ __forceinline__ void mma_tf32(float* d, const uint32_t* a,
                                         uint32_t b0, uint32_t b1) {
    asm volatile(
        "mma.sync.aligned.m16n8k8.row.col.f32.tf32.tf32.f32 "
        "{%0,%1,%2,%3},{%4,%5,%6,%7},{%8,%9},{%0,%1,%2,%3};"
        : "+f"(d[0]), "+f"(d[1]), "+f"(d[2]), "+f"(d[3])
        : "r"(a[0]), "r"(a[1]), "r"(a[2]), "r"(a[3]), "r"(b0), "r"(b1));
}

// ---------------- zero adjacency + edge dtype detection ---------------------
__global__ void zeroA_kernel(const int* __restrict__ ei) {
    if (blockIdx.x == 0 && threadIdx.x < 32) {
        int lane = threadIdx.x;
        int nz = 0;
        for (int i = lane; i < 512; i += 32) nz |= ei[2*i + 1];
        unsigned any = __ballot_sync(0xffffffffu, nz != 0);
        if (lane == 0) g_mode = (any == 0);
    }
    int n = G*NPG*NPG/4;
    float4* p = (float4*)g_A;
    float4 z = make_float4(0.f, 0.f, 0.f, 0.f);
    for (int i = blockIdx.x*blockDim.x + threadIdx.x; i < n; i += gridDim.x*blockDim.x)
        p[i] = z;
}

__global__ void edge_kernel(const int* __restrict__ ei, int E) {
    int e = blockIdx.x*blockDim.x + threadIdx.x;
    if (e >= E) return;
    int s, d;
    if (g_mode) { s = ei[2*e]; d = ei[2*(E + e)]; }   // int64 storage
    else        { s = ei[e];   d = ei[E + e];      }  // int32 storage
    if ((unsigned)s >= NTOT || (unsigned)d >= NTOT) return;
    int g  = d / NPG;
    int sl = s - g*NPG;
    int dl = d - g*NPG;
    if ((unsigned)sl >= NPG) return;
    atomicAdd(&g_A[(size_t)(g*NPG + dl)*NPG + sl], 1.0f);
}

// ---------------- node GEMM (3xTF32 mma): X[N,KD] @ [Wl|Wr] -> out[N,128] ----
// 64 rows/block, 8 warps: warp = 16 rows x 64 cols. 3-pass tf32 ~ fp32 accuracy.
template<int KD, bool RELU, int INSEL, int OUTSEL>
__global__ __launch_bounds__(256) void gemm_mma(const float* __restrict__ Xext,
                                                const float* __restrict__ Wl,
                                                const float* __restrict__ Wr) {
    constexpr int KP96 = ((KD + 15)/16)*16;
    constexpr int NST  = KP96/16;
    __shared__ float    xs[KP96*68];      // A transposed [k][row(64)+pad]
    __shared__ uint32_t whi[16*128];      // W stage, tf32 hi
    __shared__ uint32_t wlo[16*128];      // W stage, tf32 lo

    const float* X = INSEL ? (const float*)g_H1 : Xext;
    float* out = OUTSEL ? g_RW : g_PQ;
    int t = threadIdx.x;
    int r0blk = blockIdx.x * 64;

    // stage A (transposed, relu optional)
    for (int idx = t; idx < 64*KD; idx += 256) {
        int r = idx / KD, k = idx - r*KD;
        float v = X[(size_t)(r0blk + r)*KD + k];
        if (RELU) v = fmaxf(v, 0.f);
        xs[k*68 + r] = v;
    }
    if (KP96 > KD) {  // zero k padding
        for (int idx = t; idx < (KP96-KD)*68; idx += 256)
            xs[(KD + idx/68)*68 + (idx - (idx/68)*68)] = 0.f;
    }

    int lane = t & 31, wid = t >> 5;
    int gid = lane >> 2, tig = lane & 3;
    int rbase = (wid >> 1) * 16;
    int cbase = (wid & 1) * 64;

    float acc[8][4];
    #pragma unroll
    for (int i = 0; i < 8; i++)
        #pragma unroll
        for (int j = 0; j < 4; j++) acc[i][j] = 0.f;

    for (int s = 0; s < NST; s++) {
        int kt = s*16;
        __syncthreads();   // protects prev-stage whi/wlo reads; 1st iter covers xs
        for (int idx = t; idx < 16*128; idx += 256) {
            int kk = idx >> 7, c = idx & 127;
            int kg = kt + kk;
            float w = 0.f;
            if (kg < KD) w = (c < 64) ? Wl[kg*64 + c] : Wr[kg*64 + (c - 64)];
            uint32_t h, l; split_tf32(w, h, l);
            whi[idx] = h; wlo[idx] = l;
        }
        __syncthreads();

        #pragma unroll
        for (int kt2 = 0; kt2 < 16; kt2 += 8) {
            int kA = kt + kt2;
            float a0 = xs[(kA + tig)*68     + rbase + gid];
            float a1 = xs[(kA + tig)*68     + rbase + gid + 8];
            float a2 = xs[(kA + tig + 4)*68 + rbase + gid];
            float a3 = xs[(kA + tig + 4)*68 + rbase + gid + 8];
            uint32_t ah[4], al[4];
            split_tf32(a0, ah[0], al[0]);
            split_tf32(a1, ah[1], al[1]);
            split_tf32(a2, ah[2], al[2]);
            split_tf32(a3, ah[3], al[3]);
            #pragma unroll
            for (int nt = 0; nt < 8; nt++) {
                int col = cbase + nt*8 + gid;
                uint32_t b0h = whi[(kt2 + tig)*128 + col];
                uint32_t b1h = whi[(kt2 + tig + 4)*128 + col];
                uint32_t b0l = wlo[(kt2 + tig)*128 + col];
                uint32_t b1l = wlo[(kt2 + tig + 4)*128 + col];
                mma_tf32(acc[nt], ah, b0h, b1h);   // hi*hi
                mma_tf32(acc[nt], ah, b0l, b1l);   // hi*lo
                mma_tf32(acc[nt], al, b0h, b1h);   // lo*hi
            }
        }
    }

    // epilogue: d mapping c0:(gid,2*tig) c1:+1col c2:(gid+8,2*tig) c3:+1col
    #pragma unroll
    for (int nt = 0; nt < 8; nt++) {
        int col  = cbase + nt*8 + 2*tig;
        size_t r0 = (size_t)(r0blk + rbase + gid);
        *(float2*)&out[r0*128 + col]       = make_float2(acc[nt][0], acc[nt][1]);
        *(float2*)&out[(r0 + 8)*128 + col] = make_float2(acc[nt][2], acc[nt][3]);
    }
}

// ---------------- aggr conv1: h1 = mean + skip + bias -> g_H1 (+d_out tail) -
__global__ __launch_bounds__(256) void aggr_conv1(const float* __restrict__ bias,
                                                  float* __restrict__ extra) {
    __shared__ float As[NPG*APAD];
    __shared__ float inv[NPG];
    int g = blockIdx.x;
    int t = threadIdx.x;

    for (int idx = t; idx < NPG*NPG; idx += 256) {
        int row = idx / NPG, col = idx - row*NPG;
        As[row*APAD + col] = g_A[(size_t)g*NPG*NPG + idx];
    }
    if (t < NPG*2) As[(t >> 1)*APAD + NPG + (t & 1)] = 0.f;
    __syncthreads();

    {   // per-row sums -> inverse
        int wid = t >> 5, lane = t & 31;
        for (int row = wid; row < NPG; row += 8) {
            float s = 0.f;
            for (int j = lane; j < NPG; j += 32) s += As[row*APAD + j];
            #pragma unroll
            for (int o = 16; o; o >>= 1) s += __shfl_xor_sync(0xffffffffu, s, o);
            if (lane == 0) inv[row] = 1.0f / fmaxf(s, 1.0f);
        }
    }
    __syncthreads();

    int c = t & 63, rg = t >> 6;
    float acc[23];
    #pragma unroll
    for (int i = 0; i < 23; i++) acc[i] = 0.f;

    const float* Pg = g_PQ + (size_t)g*NPG*128;
    for (int j = 0; j < 88; j += 4) {
        float w0 = __ldg(&Pg[(j+0)*128 + c]);
        float w1 = __ldg(&Pg[(j+1)*128 + c]);
        float w2 = __ldg(&Pg[(j+2)*128 + c]);
        float w3 = __ldg(&Pg[(j+3)*128 + c]);
        #pragma unroll
        for (int i = 0; i < 23; i++) {
            int row = rg + 4*i;
            if (row < NPG) {
                float4 a = *(const float4*)&As[row*APAD + j];
                acc[i] += a.x*w0 + a.y*w1 + a.z*w2 + a.w*w3;
            }
        }
    }
    {
        float w0 = __ldg(&Pg[88*128 + c]);
        float w1 = __ldg(&Pg[89*128 + c]);
        #pragma unroll
        for (int i = 0; i < 23; i++) {
            int row = rg + 4*i;
            if (row < NPG)
                acc[i] += As[row*APAD + 88]*w0 + As[row*APAD + 89]*w1;
        }
    }
    float bc = bias[c];
    #pragma unroll
    for (int i = 0; i < 23; i++) {
        int row = rg + 4*i;
        if (row < NPG) {
            int n = g*NPG + row;
            float v = acc[i]*inv[row] + Pg[row*128 + 64 + c] + bc;
            g_H1[(size_t)n*HC + c] = v;
            if (extra) extra[(size_t)n*HC + c] = v;
        }
    }
}

// ---------------- aggr conv2 + sort-pool fused -> g_pool --------------------
__global__ __launch_bounds__(256) void aggr_conv2_pool(const float* __restrict__ bias) {
    __shared__ float As[NPG*APAD];
    __shared__ float inv[NPG];
    __shared__ float key[NPG];
    __shared__ int   rrank[NPG];
    int g = blockIdx.x;
    int t = threadIdx.x;

    for (int idx = t; idx < NPG*NPG; idx += 256) {
        int row = idx / NPG, col = idx - row*NPG;
        As[row*APAD + col] = g_A[(size_t)g*NPG*NPG + idx];
    }
    if (t < NPG*2) As[(t >> 1)*APAD + NPG + (t & 1)] = 0.f;
    __syncthreads();

    {
        int wid = t >> 5, lane = t & 31;
        for (int row = wid; row < NPG; row += 8) {
            float s = 0.f;
            for (int j = lane; j < NPG; j += 32) s += As[row*APAD + j];
            #pragma unroll
            for (int o = 16; o; o >>= 1) s += __shfl_xor_sync(0xffffffffu, s, o);
            if (lane == 0) inv[row] = 1.0f / fmaxf(s, 1.0f);
        }
    }
    __syncthreads();

    int c = t & 63, rg = t >> 6;
    float acc[23];
    #pragma unroll
    for (int i = 0; i < 23; i++) acc[i] = 0.f;

    const float* Pg = g_RW + (size_t)g*NPG*128;
    for (int j = 0; j < 88; j += 4) {
        float w0 = __ldg(&Pg[(j+0)*128 + c]);
        float w1 = __ldg(&Pg[(j+1)*128 + c]);
        float w2 = __ldg(&Pg[(j+2)*128 + c]);
        float w3 = __ldg(&Pg[(j+3)*128 + c]);
        #pragma unroll
        for (int i = 0; i < 23; i++) {
            int row = rg + 4*i;
            if (row < NPG) {
                float4 a = *(const float4*)&As[row*APAD + j];
                acc[i] += a.x*w0 + a.y*w1 + a.z*w2 + a.w*w3;
            }
        }
    }
    {
        float w0 = __ldg(&Pg[88*128 + c]);
        float w1 = __ldg(&Pg[89*128 + c]);
        #pragma unroll
        for (int i = 0; i < 23; i++) {
            int row = rg + 4*i;
            if (row < NPG)
                acc[i] += As[row*APAD + 88]*w0 + As[row*APAD + 89]*w1;
        }
    }
    float bc = bias[c];
    #pragma unroll
    for (int i = 0; i < 23; i++) {
        int row = rg + 4*i;
        if (row < NPG) {
            float v = acc[i]*inv[row] + Pg[row*128 + 64 + c] + bc;
            acc[i] = v;                          // keep h2 value in regs
            if (c == 63) key[row] = v;           // sort key channel
        }
    }
    __syncthreads();

    // stable desc rank by counting
    if (t < NPG) {
        float v = key[t];
        int rank = 0;
        for (int j = 0; j < NPG; j++) {
            float u = key[j];
            rank += (u > v) || (u == v && j < t);
        }
        rrank[t] = rank;
    }
    __syncthreads();

    // scatter top-KP rows into g_pool[g][rank][c]
    #pragma unroll
    for (int i = 0; i < 23; i++) {
        int row = rg + 4*i;
        if (row < NPG) {
            int rk = rrank[row];
            if (rk < KP)
                g_pool[(size_t)g*POOLW + rk*HC + c] = acc[i];
        }
    }
}

// ---------------- final: pool @ Wl1 + bl1, @ Wl2 + bl2, sigmoid -------------
__global__ __launch_bounds__(256) void final_kernel(const float* __restrict__ Wl1,
                                                    const float* __restrict__ bl1,
                                                    const float* __restrict__ Wl2,
                                                    const float* __restrict__ bl2,
                                                    float* __restrict__ outG) {
    __shared__ float ws[64*64];
    __shared__ float ps[8*64];
    __shared__ float pbuf[8*64];
    int t = threadIdx.x;
    int g0 = blockIdx.x * 8;
    int c = t & 63, gi = t >> 6;
    float acc0 = 0.f, acc1 = 0.f;

    for (int chunk = 0; chunk < POOLW/64; chunk++) {
        int m0 = chunk*64;
        __syncthreads();
        for (int idx = t; idx < 64*64; idx += 256)
            ws[idx] = Wl1[(size_t)(m0 + (idx >> 6))*64 + (idx & 63)];
        for (int idx = t; idx < 8*64; idx += 256) {
            int gg = idx >> 6, mm = idx & 63;
            ps[idx] = g_pool[(size_t)(g0 + gg)*POOLW + m0 + mm];
        }
        __syncthreads();
        #pragma unroll
        for (int kk = 0; kk < 64; kk++) {
            float w = ws[kk*64 + c];
            acc0 += ps[gi*64 + kk] * w;
            acc1 += ps[(gi+4)*64 + kk] * w;
        }
    }
    __syncthreads();
    pbuf[gi*64 + c]     = acc0 + bl1[c];
    pbuf[(gi+4)*64 + c] = acc1 + bl1[c];
    __syncthreads();
    int w = t >> 5, lane = t & 31;
    float v = pbuf[w*64 + lane]*Wl2[lane] + pbuf[w*64 + lane + 32]*Wl2[lane + 32];
    #pragma unroll
    for (int o = 16; o; o >>= 1) v += __shfl_xor_sync(0xffffffffu, v, o);
    if (lane == 0) outG[g0 + w] = 1.f / (1.f + expf(-(v + bl2[0])));
}

// ---------------------------------------------------------------------------
extern "C" void kernel_launch(void* const* d_in, const int* in_sizes, int n_in,
                              void* d_out, int out_size) {
    const float *x = 0, *W1l = 0, *W1r = 0, *W2l = 0, *W2r = 0;
    const float *Wl1 = 0, *bl2 = 0;
    const int   *ei = 0;
    int i5760 = 0, i4096 = 0;
    int idx64[8]; int n64 = 0;

    for (int i = 0; i < n_in; i++) {
        int sz = in_sizes[i];
        const float* p = (const float*)d_in[i];
        switch (sz) {
            case 4147200: x   = p; break;                       // [46080,90]
            case 1843200: ei  = (const int*)d_in[i]; break;     // [2,921600]
            case  286720: Wl1 = p; break;                       // [4480,64]
            case    5760: if (i5760++ == 0) W1l = p; else W1r = p; break;
            case    4096: if (i4096++ == 0) W2l = p; else W2r = p; break;
            case      64: if (n64 < 8) idx64[n64++] = i; break; // b1,b2,bl1,Wl2
            case       1: bl2 = p; break;
            default: break;                                     // batch unused
        }
    }
    const float *b1, *b2, *bl1, *Wl2;
    if (n_in > 0 && in_sizes[0] == 5760) {          // alphabetical (W* first)
        Wl2 = (const float*)d_in[idx64[0]];
        b1  = (const float*)d_in[idx64[1]];
        b2  = (const float*)d_in[idx64[2]];
        bl1 = (const float*)d_in[idx64[3]];
    } else {                                        // dict / signature order
        b1  = (const float*)d_in[idx64[0]];
        b2  = (const float*)d_in[idx64[1]];
        bl1 = (const float*)d_in[idx64[2]];
        Wl2 = (const float*)d_in[idx64[3]];
    }

    float* outG = (float*)d_out;
    float* xtp  = (out_size >= G + NTOT*HC) ? (float*)d_out + G : (float*)0;
    int E = 1843200 / 2;

    // (1) zero adjacency + detect edge dtype
    zeroA_kernel<<<2048, 512>>>(ei);
    // (2) edge counts
    edge_kernel<<<(E + 255)/256, 256>>>(ei, E);
    // (3) conv1 projections (3xTF32 tensor cores)
    gemm_mma<90, false, 0, 0><<<NTOT/64, 256>>>(x, W1l, W1r);
    // (4) conv1 aggregation  [<- ncu capture slot]
    aggr_conv1<<<G, 256>>>(b1, xtp);
    // (5) conv2 projections (relu on load)
    gemm_mma<64, true, 1, 1><<<NTOT/64, 256>>>((const float*)0, W2l, W2r);
    // (6) conv2 aggregation + sort-pool fused
    aggr_conv2_pool<<<G, 256>>>(b2);
    // (7) MLP head
    final_kernel<<<G/8, 256>>>(Wl1, bl1, Wl2, bl2, outG);
}